// round 3
// baseline (speedup 1.0000x reference)
#include <cuda_runtime.h>
#include <cuda_bf16.h>
#include <math.h>

// HMM forward: 511 serial steps of batched log-space matvec.
// Layout: 16 clusters x 8 CTAs. Cluster = 4 batches (fully self-contained
// recurrence -> only cluster.sync needed). CTA = 64-row slice of W in smem.
// W = (A^T + eps)/(colmax + eps) precomputed once (== exp(logA_T - rowmax)).

#define HH 512
#define VV 50257
#define BB 64
#define TT 512
#define HS 8          // H slices (CTAs per cluster)
#define NCLUST 16     // batch groups

using ull = unsigned long long;

// ---- device scratch (static allocations only; no cudaMalloc anywhere) ----
__device__ float g_Wlay[HH * HH];          // [hs][kp:256][r:64][2] packed pairs
__device__ float g_Ainv[HH];
__device__ float g_wmax[HH];
__device__ float g_Alpha[2][BB * HH];      // double-buffered state
__device__ float g_Pmax[2][BB * HS];       // per-(batch, slice) partial max

#define CLUSTER_SYNC() do { \
  asm volatile("barrier.cluster.arrive.aligned;" ::: "memory"); \
  asm volatile("barrier.cluster.wait.aligned;"   ::: "memory"); \
} while (0)

__device__ __forceinline__ ull ffma2(ull a, ull b, ull c) {
  ull d;
  asm("fma.rn.f32x2 %0, %1, %2, %3;" : "=l"(d) : "l"(a), "l"(b), "l"(c));
  return d;
}

__device__ __forceinline__ float psum2(ull u) {
  float lo = __uint_as_float((unsigned)u);
  float hi = __uint_as_float((unsigned)(u >> 32));
  return lo + hi;
}

// ---- prologue 1: column max of alpha_exp (= rowmax of logA_T), inverse, wmax
__global__ void colmax_kernel(const float* __restrict__ A) {
  int i = blockIdx.x * blockDim.x + threadIdx.x;
  if (i >= HH) return;
  float m = 0.0f;
  #pragma unroll 8
  for (int j = 0; j < HH; j++) m = fmaxf(m, A[j * HH + i]);
  float d = m + 1e-12f;
  g_Ainv[i] = 1.0f / d;
  g_wmax[i] = logf(d);
}

// ---- prologue 2: W[i][j] = (A[j][i]+eps) * Ainv[i], stored slice-packed
__global__ void wfill_kernel(const float* __restrict__ A) {
  int idx = blockIdx.x * blockDim.x + threadIdx.x;   // idx = j*H + i
  if (idx >= HH * HH) return;
  int j = idx >> 9, i = idx & (HH - 1);
  float v = (A[idx] + 1e-12f) * g_Ainv[i];
  int hs = i >> 6, r = i & 63, kp = j >> 1, c = j & 1;
  g_Wlay[hs * 32768 + kp * 128 + r * 2 + c] = v;
}

// ---- main persistent kernel ----
extern __shared__ float sW[];  // 32768 floats = 128KB: Wp[kp:256][r:64] float2

__global__ void __cluster_dims__(8, 1, 1) __launch_bounds__(256, 1)
hmm_main(const float* __restrict__ beta, const float* __restrict__ gamma,
         const int* __restrict__ ids, float* __restrict__ out) {
  __shared__ float2 xs[256][4];     // xs[kp][b] = (x[2kp], x[2kp+1]) for batch b
  __shared__ float4 red[8 * 64];    // red[warp][r] = partials for 4 batches
  __shared__ int    sids[4][TT];
  __shared__ float  swmax[64];
  __shared__ float  smax2[8];

  const int tid = threadIdx.x;
  const int hs = blockIdx.x & 7;        // slice (== cluster cta rank)
  const int bg = blockIdx.x >> 3;       // batch group

  // load W slice into smem (stays resident for all 511 steps)
  {
    const float4* src = (const float4*)(g_Wlay + hs * 32768);
    float4* dst = (float4*)sW;
    for (int i = tid; i < 8192; i += 256) dst[i] = src[i];
  }
  for (int i = tid; i < 4 * TT; i += 256) {
    int b = i >> 9, t = i & (TT - 1);
    sids[b][t] = ids[(bg * 4 + b) * TT + t];
  }
  if (tid < 64) swmax[tid] = g_wmax[hs * 64 + tid];
  __syncthreads();

  const int b     = tid >> 6;           // 0..3 (vec-mapping batch)
  const int r     = tid & 63;           // 0..63 (vec-mapping row)
  const int h     = hs * 64 + r;
  const int bglob = bg * 4 + b;
  const int warp  = tid >> 5, lane = tid & 31;

  // ---- init: alpha0 = log(gamma) + beta[:, ids[:,0]] ----
  {
    float a0 = __logf(gamma[h]) + __ldg(&beta[(size_t)h * VV + sids[b][0]]);
    __stcg(&g_Alpha[0][bglob * HH + h], a0);
    float m = a0;
    #pragma unroll
    for (int o = 16; o > 0; o >>= 1) m = fmaxf(m, __shfl_xor_sync(0xffffffffu, m, o));
    if (lane == 0) smax2[warp] = m;
    __syncthreads();
    if (r == 0)
      __stcg(&g_Pmax[0][bglob * HS + hs], fmaxf(smax2[2 * b], smax2[2 * b + 1]));
  }
  CLUSTER_SYNC();

  int p = 0;
  for (int t = 1; t < TT; t++) {
    // ---- phase 1 (vec mapping): gather beta early, amax, exp, pack x ----
    float bsel = __ldg(&beta[(size_t)h * VV + sids[b][t]]);  // consumed ~1.5K cyc later

    float amax = -3.4e38f;
    #pragma unroll
    for (int j = 0; j < 8; j++)
      amax = fmaxf(amax, __ldcg(&g_Pmax[p][bglob * HS + j]));

    #pragma unroll
    for (int i = 0; i < 8; i++) {
      int k = i * 64 + r;
      float a = __ldcg(&g_Alpha[p][bglob * HH + k]);
      float x = __expf(a - amax);
      ((float*)xs)[(k >> 1) * 8 + b * 2 + (k & 1)] = x;
    }
    __syncthreads();

    // ---- phase 2 (mma mapping): warp = K-chunk of 64, lane = rows {l, l+32}
    ull acc0 = 0, acc1 = 0, acc2 = 0, acc3 = 0, acc4 = 0, acc5 = 0, acc6 = 0, acc7 = 0;
    {
      const ull* wp = (const ull*)sW + warp * 32 * 64 + lane;
      const ulonglong2* xp = (const ulonglong2*)xs + warp * 32 * 2;
      #pragma unroll 8
      for (int kpi = 0; kpi < 32; kpi++) {
        ull w0 = wp[0];
        ull w1 = wp[32];
        ulonglong2 xa = xp[0];   // batches 0,1 (warp-uniform broadcast)
        ulonglong2 xb = xp[1];   // batches 2,3
        wp += 64; xp += 2;
        acc0 = ffma2(w0, xa.x, acc0);
        acc1 = ffma2(w0, xa.y, acc1);
        acc2 = ffma2(w0, xb.x, acc2);
        acc3 = ffma2(w0, xb.y, acc3);
        acc4 = ffma2(w1, xa.x, acc4);
        acc5 = ffma2(w1, xa.y, acc5);
        acc6 = ffma2(w1, xb.x, acc6);
        acc7 = ffma2(w1, xb.y, acc7);
      }
    }
    red[warp * 64 + lane]      = make_float4(psum2(acc0), psum2(acc1), psum2(acc2), psum2(acc3));
    red[warp * 64 + lane + 32] = make_float4(psum2(acc4), psum2(acc5), psum2(acc6), psum2(acc7));
    __syncthreads();

    // ---- phase 3 (vec mapping): reduce 8 K-chunk partials, log, emit ----
    const float* redf = (const float*)red;
    float z = 0.0f;
    #pragma unroll
    for (int w = 0; w < 8; w++) z += redf[(w * 64 + r) * 4 + b];

    float anew = __logf(z) + amax + swmax[r] + bsel;

    if (t == TT - 1) {
      out[bglob * HH + h] = anew;
    } else {
      __stcg(&g_Alpha[p ^ 1][bglob * HH + h], anew);
      float m = anew;
      #pragma unroll
      for (int o = 16; o > 0; o >>= 1) m = fmaxf(m, __shfl_xor_sync(0xffffffffu, m, o));
      if (lane == 0) smax2[warp] = m;
      __syncthreads();
      if (r == 0)
        __stcg(&g_Pmax[p ^ 1][bglob * HS + hs], fmaxf(smax2[2 * b], smax2[2 * b + 1]));
      CLUSTER_SYNC();   // release alpha/pmax writes; one sync per step
      p ^= 1;
    }
  }
}

extern "C" void kernel_launch(void* const* d_in, const int* in_sizes, int n_in,
                              void* d_out, int out_size) {
  const float* A     = (const float*)d_in[0];   // alpha_exp (H,H)
  const float* beta  = (const float*)d_in[1];   // (H,V)
  const float* gamma = (const float*)d_in[2];   // (1,H)
  const int*   ids   = (const int*)d_in[3];     // (B,T) int32
  float* out = (float*)d_out;                   // (B,H) f32

  cudaFuncSetAttribute(hmm_main, cudaFuncAttributeMaxDynamicSharedMemorySize,
                       132 * 1024);

  colmax_kernel<<<4, 128>>>(A);
  wfill_kernel<<<1024, 256>>>(A);
  hmm_main<<<128, 256, 131072>>>(beta, gamma, ids, out);
}